// round 9
// baseline (speedup 1.0000x reference)
#include <cuda_runtime.h>
#include <cstdint>

#define G 32           // groups
#define CG 2           // channels per group (C=64)
#define MAXB 1024      // max supported batch size for scratch sizing
#define EPSF 1e-5f
#define U 8            // points per warp-iteration
#define NSM 148        // sm count floor
#define BPSM 5         // resident blocks per SM at 256 thr / <=51 regs

// Scratch (device globals: allocation-free per harness rules).
// Zero-initialized at load; the fused finalize (last stats block) self-resets
// everything it consumed, so every graph replay sees zeroed accumulators.
__device__ float  g_s1[MAXB * G];
__device__ float  g_s2[MAXB * G];
__device__ float  g_cnt[MAXB];
__device__ unsigned int g_done = 0;
__device__ __align__(16) float2 g_mi[MAXB * G];   // (mean, inv) per (b, g)

// packed helpers (f32x2 — PTX-only on sm_103a)
__device__ __forceinline__ unsigned long long pack_f32x2(float lo, float hi) {
    unsigned long long r;
    asm("mov.b64 %0, {%1, %2};" : "=l"(r) : "f"(lo), "f"(hi));
    return r;
}
__device__ __forceinline__ void unpack_f32x2(unsigned long long v, float& lo, float& hi) {
    asm("mov.b64 {%0, %1}, %2;" : "=f"(lo), "=f"(hi) : "l"(v));
}
__device__ __forceinline__ void acc_if_eq(unsigned long long& acc, int b, int bb,
                                          unsigned long long vp) {
    asm("{\n\t"
        ".reg .pred p;\n\t"
        "setp.eq.s32 p, %1, %2;\n\t"
        "@p add.rn.f32x2 %0, %0, %3;\n\t"
        "}" : "+l"(acc) : "r"(b), "r"(bb), "l"(vp));
}

// ---------------------------------------------------------------------------
// Kernel 1: stats (+ fused finalize in the last block to finish).
// Warp-per-point, lane L owns group L. Fast path (B<=8): software-pipelined
// rotation — consume xb[j], immediately reload it with the next chunk's data,
// so 8 loads stay in flight throughout binning (no extra registers).
// ---------------------------------------------------------------------------
__global__ void __launch_bounds__(256, BPSM) stats_kernel(const float* __restrict__ feat,
                                                          const int* __restrict__ bidx,
                                                          int N, const int* __restrict__ Bp) {
    const int B = *Bp;
    const int lane   = threadIdx.x & 31;
    const int gwarp  = (blockIdx.x * blockDim.x + threadIdx.x) >> 5;
    const int nwarps = (gridDim.x * blockDim.x) >> 5;

    if (B <= 8) {
        unsigned long long acc[8];   // packed (sum, sumsq) per bin
#pragma unroll
        for (int bb = 0; bb < 8; bb++) acc[bb] = 0ULL;
        float cnt = 0.0f;            // lane L accumulates count of bin L (L<8)

        int base = gwarp * U;
        const int stride = nwarps * U;

        if (base + (U - 1) < N) {
            // prologue: load first chunk
            int myb = (lane < U) ? __ldg(bidx + base + lane) : 0;
            float2 xb[U];
#pragma unroll
            for (int j = 0; j < U; j++)
                xb[j] = __ldg(reinterpret_cast<const float2*>(
                              feat + (size_t)(base + j) * 64) + lane);

            int next = base + stride;
            while (next + (U - 1) < N) {
                const int nmyb = (lane < U) ? __ldg(bidx + next + lane) : 0;
#pragma unroll
                for (int j = 0; j < U; j++) {
                    const int b = __shfl_sync(0xFFFFFFFFu, myb, j);
                    const float v  = xb[j].x + xb[j].y;
                    const float v2 = fmaf(xb[j].x, xb[j].x, xb[j].y * xb[j].y);
                    // rotate: reload this slot with next chunk's point j
                    xb[j] = __ldg(reinterpret_cast<const float2*>(
                                  feat + (size_t)(next + j) * 64) + lane);
                    const unsigned long long vp = pack_f32x2(v, v2);
#pragma unroll
                    for (int bb = 0; bb < 8; bb++) acc_if_eq(acc[bb], b, bb, vp);
                    if (lane == b) cnt += 1.0f;
                }
                myb = nmyb;
                next += stride;
            }
            // drain: bin the last loaded chunk
#pragma unroll
            for (int j = 0; j < U; j++) {
                const int b = __shfl_sync(0xFFFFFFFFu, myb, j);
                const float v  = xb[j].x + xb[j].y;
                const float v2 = fmaf(xb[j].x, xb[j].x, xb[j].y * xb[j].y);
                const unsigned long long vp = pack_f32x2(v, v2);
#pragma unroll
                for (int bb = 0; bb < 8; bb++) acc_if_eq(acc[bb], b, bb, vp);
                if (lane == b) cnt += 1.0f;
            }
            base = next;   // first unprocessed index for the tail
        }
        // tail (at most one warp has base < N here; partial final chunk)
        for (; base < N; base++) {
            const int b = __ldg(bidx + base);
            const float2 x = __ldg(reinterpret_cast<const float2*>(
                                   feat + (size_t)base * 64) + lane);
            const unsigned long long vp =
                pack_f32x2(x.x + x.y, fmaf(x.x, x.x, x.y * x.y));
#pragma unroll
            for (int bb = 0; bb < 8; bb++) acc_if_eq(acc[bb], b, bb, vp);
            if (lane == b) cnt += 1.0f;
        }

        // Block-level reduction in shared, then <=520 global atomics per block
        __shared__ float sh1[8 * G];
        __shared__ float sh2[8 * G];
        __shared__ float shc[8];
        for (int i = threadIdx.x; i < 8 * G; i += blockDim.x) { sh1[i] = 0.0f; sh2[i] = 0.0f; }
        if (threadIdx.x < 8) shc[threadIdx.x] = 0.0f;
        __syncthreads();
#pragma unroll
        for (int bb = 0; bb < 8; bb++) {
            float a1, a2;
            unpack_f32x2(acc[bb], a1, a2);
            atomicAdd(&sh1[bb * G + lane], a1);
            atomicAdd(&sh2[bb * G + lane], a2);
        }
        if (lane < 8 && cnt != 0.0f) atomicAdd(&shc[lane], cnt);
        __syncthreads();
        const int i = threadIdx.x;            // exactly 256 = 8*G entries
        if (sh1[i] != 0.0f || sh2[i] != 0.0f) {
            atomicAdd(&g_s1[i], sh1[i]);
            atomicAdd(&g_s2[i], sh2[i]);
        }
        if (i < 8 && shc[i] != 0.0f) atomicAdd(&g_cnt[i], shc[i]);
    } else {
        // Generic fallback: per-point global atomics (rare path)
        for (int p = gwarp; p < N; p += nwarps) {
            const int b = __ldg(bidx + p);
            if (b < 0 || b >= MAXB) continue;
            const float2 x = __ldg(reinterpret_cast<const float2*>(
                                   feat + (size_t)p * 64) + lane);
            atomicAdd(&g_s1[b * G + lane], x.x + x.y);
            atomicAdd(&g_s2[b * G + lane], fmaf(x.x, x.x, x.y * x.y));
            if (lane == 0) atomicAdd(&g_cnt[b], 1.0f);
        }
    }

    // ---- fused finalize: the last block to finish computes (mean, inv) and
    // resets all accumulators + the ticket for the next graph replay.
    __shared__ unsigned int s_ticket;
    __threadfence();
    if (threadIdx.x == 0) s_ticket = atomicAdd(&g_done, 1u);
    __syncthreads();
    if (s_ticket == (unsigned)(gridDim.x - 1)) {
        __threadfence();
        int BB = B < 1 ? 1 : (B > MAXB ? MAXB : B);
        for (int i = threadIdx.x; i < BB * G; i += blockDim.x) {
            const int b = i >> 5;
            const float c    = fmaxf(g_cnt[b] * (float)CG, 1.0f);
            const float mean = g_s1[i] / c;
            const float var  = g_s2[i] / c - mean * mean;
            const float inv  = rsqrtf(var + EPSF);
            g_mi[i] = make_float2(mean, inv);
            g_s1[i] = 0.0f;
            g_s2[i] = 0.0f;
        }
        __syncthreads();
        for (int b = threadIdx.x; b < BB; b += blockDim.x) g_cnt[b] = 0.0f;
        if (threadIdx.x == 0) g_done = 0;
    }
}

// ---------------------------------------------------------------------------
// Kernel 2: normalize — float2 3-phase version (best measured) with the same
// rotation pipelining: compute+store point j, then reload feat/table slot j
// with the next chunk's data.
//   out = (x - mean) * inv * w + bias
// ---------------------------------------------------------------------------
__global__ void __launch_bounds__(256, BPSM) normalize_kernel(const float* __restrict__ feat,
                                                              const int* __restrict__ bidx,
                                                              const float* __restrict__ w,
                                                              const float* __restrict__ bias,
                                                              float* __restrict__ out, int N) {
    const int lane   = threadIdx.x & 31;
    const int gwarp  = (blockIdx.x * blockDim.x + threadIdx.x) >> 5;
    const int nwarps = (gridDim.x * blockDim.x) >> 5;

    // Per-lane channel constants (2 channels per lane), loaded once.
    const float2 wv = __ldg(reinterpret_cast<const float2*>(w) + lane);
    const float2 bv = __ldg(reinterpret_cast<const float2*>(bias) + lane);

    int base = gwarp * U;
    const int stride = nwarps * U;

    if (base + (U - 1) < N) {
        // prologue
        int myb = (lane < U) ? __ldg(bidx + base + lane) : 0;
        float2 xb[U], mi[U];
#pragma unroll
        for (int j = 0; j < U; j++)
            xb[j] = __ldcs(reinterpret_cast<const float2*>(
                           feat + (size_t)(base + j) * 64) + lane);
#pragma unroll
        for (int j = 0; j < U; j++) {
            const int b = __shfl_sync(0xFFFFFFFFu, myb, j);
            mi[j] = __ldg(&g_mi[b * G + lane]);
        }

        int next = base + stride;
        while (next + (U - 1) < N) {
            const int nmyb = (lane < U) ? __ldg(bidx + next + lane) : 0;
#pragma unroll
            for (int j = 0; j < U; j++) {
                float2 y;
                y.x = fmaf(xb[j].x - mi[j].x, mi[j].y * wv.x, bv.x);
                y.y = fmaf(xb[j].y - mi[j].x, mi[j].y * wv.y, bv.y);
                __stcs(reinterpret_cast<float2*>(out + (size_t)(base + j) * 64) + lane, y);
                // rotate: reload slot j with next chunk's data
                xb[j] = __ldcs(reinterpret_cast<const float2*>(
                               feat + (size_t)(next + j) * 64) + lane);
                const int b = __shfl_sync(0xFFFFFFFFu, nmyb, j);
                mi[j] = __ldg(&g_mi[b * G + lane]);
            }
            base = next;
            next += stride;
        }
        // drain last chunk
#pragma unroll
        for (int j = 0; j < U; j++) {
            float2 y;
            y.x = fmaf(xb[j].x - mi[j].x, mi[j].y * wv.x, bv.x);
            y.y = fmaf(xb[j].y - mi[j].x, mi[j].y * wv.y, bv.y);
            __stcs(reinterpret_cast<float2*>(out + (size_t)(base + j) * 64) + lane, y);
        }
        base = next;
    }
    // tail
    for (; base < N; base++) {
        const int b = __ldg(bidx + base);
        const float2 mi2 = __ldg(&g_mi[b * G + lane]);
        const float2 x = __ldcs(reinterpret_cast<const float2*>(
                                feat + (size_t)base * 64) + lane);
        float2 y;
        y.x = fmaf(x.x - mi2.x, mi2.y * wv.x, bv.x);
        y.y = fmaf(x.y - mi2.x, mi2.y * wv.y, bv.y);
        __stcs(reinterpret_cast<float2*>(out + (size_t)base * 64) + lane, y);
    }
}

// ---------------------------------------------------------------------------
// kernel_launch
// inputs: 0=features [N*64] f32, 1=weight [64] f32, 2=bias [64] f32,
//         3=batch_idx [N] i32, 4=batch_size [1] i32 (device scalar)
// ---------------------------------------------------------------------------
extern "C" void kernel_launch(void* const* d_in, const int* in_sizes, int n_in,
                              void* d_out, int out_size) {
    const float* feat = (const float*)d_in[0];
    const float* w    = (const float*)d_in[1];
    const float* bias = (const float*)d_in[2];
    const int*   bidx = (const int*)d_in[3];
    const int*   Bp   = (const int*)d_in[4];
    float* out = (float*)d_out;

    const int N = in_sizes[3];           // batch_idx element count == N points

    const int threads = 256;

    // Stats: oversubscribed grid -> tail balancing (best measured).
    int stats_blocks = (N + 31) / 32;
    if (stats_blocks > 1184) stats_blocks = 1184;
    if (stats_blocks < 1) stats_blocks = 1;

    // Normalize: one resident wave (best measured).
    int norm_blocks = NSM * BPSM;        // 740
    int need = (N + 31) / 32;
    if (norm_blocks > need) norm_blocks = need;
    if (norm_blocks < 1) norm_blocks = 1;

    stats_kernel<<<stats_blocks, threads>>>(feat, bidx, N, Bp);
    normalize_kernel<<<norm_blocks, threads>>>(feat, bidx, w, bias, out, N);
}

// round 10
// speedup vs baseline: 1.0503x; 1.0503x over previous
#include <cuda_runtime.h>
#include <cstdint>

#define G 32           // groups
#define CG 2           // channels per group (C=64)
#define MAXB 1024      // max supported batch size for scratch sizing
#define EPSF 1e-5f
#define U 8            // points per warp-iteration
#define NSM 148        // sm count floor
#define BPSM 5         // resident blocks per SM at 256 thr / <=51 regs

// Scratch (device globals: allocation-free per harness rules).
// Zero-initialized at load; the fused finalize (last stats block) self-resets
// everything it consumed, so every graph replay sees zeroed accumulators.
__device__ float  g_s1[MAXB * G];
__device__ float  g_s2[MAXB * G];
__device__ float  g_cnt[MAXB];
__device__ unsigned int g_done = 0;
__device__ __align__(16) float2 g_mi[MAXB * G];   // (mean, inv) per (b, g)

// packed helpers (f32x2 — PTX-only on sm_103a)
__device__ __forceinline__ unsigned long long pack_f32x2(float lo, float hi) {
    unsigned long long r;
    asm("mov.b64 %0, {%1, %2};" : "=l"(r) : "f"(lo), "f"(hi));
    return r;
}
__device__ __forceinline__ void unpack_f32x2(unsigned long long v, float& lo, float& hi) {
    asm("mov.b64 {%0, %1}, %2;" : "=f"(lo), "=f"(hi) : "l"(v));
}
__device__ __forceinline__ void acc_if_eq(unsigned long long& acc, int b, int bb,
                                          unsigned long long vp) {
    asm("{\n\t"
        ".reg .pred p;\n\t"
        "setp.eq.s32 p, %1, %2;\n\t"
        "@p add.rn.f32x2 %0, %0, %3;\n\t"
        "}" : "+l"(acc) : "r"(b), "r"(bb), "l"(vp));
}

// ---------------------------------------------------------------------------
// Kernel 1: stats (+ fused finalize in the last block to finish).
// R5 configuration (best measured): grid 1184, forward sweep, plain __ldg
// (feeds L2 so the tail of the feature array is resident for normalize),
// MLP=8 front-batched loads, packed f32x2 predicated binning.
// ---------------------------------------------------------------------------
__global__ void __launch_bounds__(256, BPSM) stats_kernel(const float* __restrict__ feat,
                                                          const int* __restrict__ bidx,
                                                          int N, const int* __restrict__ Bp) {
    const int B = *Bp;
    const int lane   = threadIdx.x & 31;
    const int gwarp  = (blockIdx.x * blockDim.x + threadIdx.x) >> 5;
    const int nwarps = (gridDim.x * blockDim.x) >> 5;

    if (B <= 8) {
        unsigned long long acc[8];   // packed (sum, sumsq) per bin
#pragma unroll
        for (int bb = 0; bb < 8; bb++) acc[bb] = 0ULL;
        float cnt = 0.0f;            // lane L accumulates count of bin L (L<8)

        int base = gwarp * U;
        const int stride = nwarps * U;
        for (; base + (U - 1) < N; base += stride) {
            const int myb = (lane < U) ? __ldg(bidx + base + lane) : 0;
            float2 xb[U];
#pragma unroll
            for (int j = 0; j < U; j++)
                xb[j] = __ldg(reinterpret_cast<const float2*>(
                              feat + (size_t)(base + j) * 64) + lane);
#pragma unroll
            for (int j = 0; j < U; j++) {
                const int b = __shfl_sync(0xFFFFFFFFu, myb, j);
                const float v  = xb[j].x + xb[j].y;
                const float v2 = fmaf(xb[j].x, xb[j].x, xb[j].y * xb[j].y);
                const unsigned long long vp = pack_f32x2(v, v2);
#pragma unroll
                for (int bb = 0; bb < 8; bb++) acc_if_eq(acc[bb], b, bb, vp);
                if (lane == b) cnt += 1.0f;
            }
        }
        for (; base < N; base++) {
            const int b = __ldg(bidx + base);
            const float2 x = __ldg(reinterpret_cast<const float2*>(
                                   feat + (size_t)base * 64) + lane);
            const unsigned long long vp =
                pack_f32x2(x.x + x.y, fmaf(x.x, x.x, x.y * x.y));
#pragma unroll
            for (int bb = 0; bb < 8; bb++) acc_if_eq(acc[bb], b, bb, vp);
            if (lane == b) cnt += 1.0f;
        }

        __shared__ float sh1[8 * G];
        __shared__ float sh2[8 * G];
        __shared__ float shc[8];
        for (int i = threadIdx.x; i < 8 * G; i += blockDim.x) { sh1[i] = 0.0f; sh2[i] = 0.0f; }
        if (threadIdx.x < 8) shc[threadIdx.x] = 0.0f;
        __syncthreads();
#pragma unroll
        for (int bb = 0; bb < 8; bb++) {
            float a1, a2;
            unpack_f32x2(acc[bb], a1, a2);
            atomicAdd(&sh1[bb * G + lane], a1);
            atomicAdd(&sh2[bb * G + lane], a2);
        }
        if (lane < 8 && cnt != 0.0f) atomicAdd(&shc[lane], cnt);
        __syncthreads();
        const int i = threadIdx.x;            // exactly 256 = 8*G entries
        if (sh1[i] != 0.0f || sh2[i] != 0.0f) {
            atomicAdd(&g_s1[i], sh1[i]);
            atomicAdd(&g_s2[i], sh2[i]);
        }
        if (i < 8 && shc[i] != 0.0f) atomicAdd(&g_cnt[i], shc[i]);
    } else {
        // Generic fallback: per-point global atomics (rare path)
        for (int p = gwarp; p < N; p += nwarps) {
            const int b = __ldg(bidx + p);
            if (b < 0 || b >= MAXB) continue;
            const float2 x = __ldg(reinterpret_cast<const float2*>(
                                   feat + (size_t)p * 64) + lane);
            atomicAdd(&g_s1[b * G + lane], x.x + x.y);
            atomicAdd(&g_s2[b * G + lane], fmaf(x.x, x.x, x.y * x.y));
            if (lane == 0) atomicAdd(&g_cnt[b], 1.0f);
        }
    }

    // ---- fused finalize: the last block to finish computes (mean, inv) and
    // resets all accumulators + the ticket for the next graph replay.
    __shared__ unsigned int s_ticket;
    __threadfence();
    if (threadIdx.x == 0) s_ticket = atomicAdd(&g_done, 1u);
    __syncthreads();
    if (s_ticket == (unsigned)(gridDim.x - 1)) {
        __threadfence();
        int BB = B < 1 ? 1 : (B > MAXB ? MAXB : B);
        for (int i = threadIdx.x; i < BB * G; i += blockDim.x) {
            const int b = i >> 5;
            const float c    = fmaxf(g_cnt[b] * (float)CG, 1.0f);
            const float mean = g_s1[i] / c;
            const float var  = g_s2[i] / c - mean * mean;
            const float inv  = rsqrtf(var + EPSF);
            g_mi[i] = make_float2(mean, inv);
            g_s1[i] = 0.0f;
            g_s2[i] = 0.0f;
        }
        __syncthreads();
        for (int b = threadIdx.x; b < BB; b += blockDim.x) g_cnt[b] = 0.0f;
        if (threadIdx.x == 0) g_done = 0;
    }
}

// ---------------------------------------------------------------------------
// Kernel 2: normalize — 3-phase float2 form, but REVERSE global sweep:
// chunks processed in descending t, so the first reads hit the ~126MB tail of
// the feature array that stats left resident in L2. Streaming hints keep the
// kernel's own traffic from evicting that carryover set prematurely.
//   out = (x - mean) * inv * w + bias
// ---------------------------------------------------------------------------
__global__ void __launch_bounds__(256, BPSM) normalize_kernel(const float* __restrict__ feat,
                                                              const int* __restrict__ bidx,
                                                              const float* __restrict__ w,
                                                              const float* __restrict__ bias,
                                                              float* __restrict__ out, int N) {
    const int lane   = threadIdx.x & 31;
    const int gwarp  = (blockIdx.x * blockDim.x + threadIdx.x) >> 5;
    const int nwarps = (gridDim.x * blockDim.x) >> 5;

    // Per-lane channel constants (2 channels per lane), loaded once.
    const float2 wv = __ldg(reinterpret_cast<const float2*>(w) + lane);
    const float2 bv = __ldg(reinterpret_cast<const float2*>(bias) + lane);

    const int base0  = gwarp * U;
    const int stride = nwarps * U;

    // Number of full chunks this warp owns.
    int T = 0;
    if (base0 <= N - U) T = (N - U - base0) / stride + 1;

    // Tail first (at most one warp has a partial final chunk).
    for (int p = base0 + T * stride; p < N; p++) {
        const int b = __ldg(bidx + p);
        const float2 mi2 = __ldg(&g_mi[b * G + lane]);
        const float2 x = __ldcs(reinterpret_cast<const float2*>(
                                feat + (size_t)p * 64) + lane);
        float2 y;
        y.x = fmaf(x.x - mi2.x, mi2.y * wv.x, bv.x);
        y.y = fmaf(x.y - mi2.x, mi2.y * wv.y, bv.y);
        __stcs(reinterpret_cast<float2*>(out + (size_t)p * 64) + lane, y);
    }

    // Main loop: descending chunk order (global back-to-front sweep).
    for (int t = T - 1; t >= 0; t--) {
        const int base = base0 + t * stride;
        // phase 1: index load + 8 independent streaming feature loads
        const int myb = (lane < U) ? __ldg(bidx + base + lane) : 0;
        float2 xb[U];
#pragma unroll
        for (int j = 0; j < U; j++)
            xb[j] = __ldcs(reinterpret_cast<const float2*>(
                           feat + (size_t)(base + j) * 64) + lane);
        // phase 2: dependent table loads, batched (L1-resident table)
        float2 mi[U];
#pragma unroll
        for (int j = 0; j < U; j++) {
            const int b = __shfl_sync(0xFFFFFFFFu, myb, j);
            mi[j] = __ldg(&g_mi[b * G + lane]);
        }
        // phase 3: compute + streaming store
#pragma unroll
        for (int j = 0; j < U; j++) {
            float2 y;
            y.x = fmaf(xb[j].x - mi[j].x, mi[j].y * wv.x, bv.x);
            y.y = fmaf(xb[j].y - mi[j].x, mi[j].y * wv.y, bv.y);
            __stcs(reinterpret_cast<float2*>(out + (size_t)(base + j) * 64) + lane, y);
        }
    }
}

// ---------------------------------------------------------------------------
// kernel_launch
// inputs: 0=features [N*64] f32, 1=weight [64] f32, 2=bias [64] f32,
//         3=batch_idx [N] i32, 4=batch_size [1] i32 (device scalar)
// ---------------------------------------------------------------------------
extern "C" void kernel_launch(void* const* d_in, const int* in_sizes, int n_in,
                              void* d_out, int out_size) {
    const float* feat = (const float*)d_in[0];
    const float* w    = (const float*)d_in[1];
    const float* bias = (const float*)d_in[2];
    const int*   bidx = (const int*)d_in[3];
    const int*   Bp   = (const int*)d_in[4];
    float* out = (float*)d_out;

    const int N = in_sizes[3];           // batch_idx element count == N points

    const int threads = 256;

    // Stats: oversubscribed grid -> tail balancing (best measured).
    int stats_blocks = (N + 31) / 32;
    if (stats_blocks > 1184) stats_blocks = 1184;
    if (stats_blocks < 1) stats_blocks = 1;

    // Normalize: one resident wave -> synchronized reverse sweep front.
    int norm_blocks = NSM * BPSM;        // 740
    int need = (N + 31) / 32;
    if (norm_blocks > need) norm_blocks = need;
    if (norm_blocks < 1) norm_blocks = 1;

    stats_kernel<<<stats_blocks, threads>>>(feat, bidx, N, Bp);
    normalize_kernel<<<norm_blocks, threads>>>(feat, bidx, w, bias, out, N);
}